// round 11
// baseline (speedup 1.0000x reference)
#include <cuda_runtime.h>
#include <cuda_fp16.h>
#include <stdint.h>
#include <math.h>

#define NT 365
#define NG 512
#define NX 256
#define HH 1024
#define KTOT 1280
#define G4 4096
#define NGHH (NG * HH)
#define NCHUNK 20                    // 4 chunks of xm (K=256) first, then 16 of h (K=1024)
#define STAGE_BYTES 32768            // A(16KB) + B(16KB)
#define NSTAGE 4
#define SMEM_ST_OFF (NSTAGE * STAGE_BYTES)
#define DSMEM_BYTES (SMEM_ST_OFF + 128 * 132 * 4)   // stages + dedicated sT = 194KB
#define NBLK 128
#define GRPSZ 32                     // CTAs per m-group barrier

// ---------------- scratch (__device__ globals; no allocation) ----------------
__device__ __half g_h[2][NGHH];                     // ping-pong, fp16
__device__ __half g_Wp[(size_t)G4 * KTOT];          // rows permuted: r' = col*4 + gate
__device__ __half g_xm[(size_t)NT * NG * NX];       // fp16
__device__ float4 g_biasp[HH];                      // per col: (bi, bf, bg, bo)
__device__ unsigned int g_bar_cnt[4 * 32];          // per m-group, padded
__device__ volatile unsigned int g_bar_gen[4 * 32];

// ---------------- PTX helpers ----------------
static __device__ __forceinline__ uint32_t smem_u32(const void* p) {
    uint32_t a;
    asm("{ .reg .u64 t; cvta.to.shared.u64 t, %1; cvt.u32.u64 %0, t; }" : "=r"(a) : "l"(p));
    return a;
}
#define SWZ(o) ((o) ^ (((o) >> 3) & 0x70))

static __device__ __forceinline__ void cp16(uint32_t dst, const void* src) {
    asm volatile("cp.async.cg.shared.global [%0], [%1], 16;" :: "r"(dst), "l"(src));
}
static __device__ __forceinline__ void cp_commit() {
    asm volatile("cp.async.commit_group;" ::: "memory");
}
template <int N>
static __device__ __forceinline__ void cp_wait() {
    asm volatile("cp.async.wait_group %0;" :: "n"(N) : "memory");
}
static __device__ __forceinline__ void ldm4(uint32_t* r, uint32_t addr) {
    asm volatile("ldmatrix.sync.aligned.m8n8.x4.shared.b16 {%0,%1,%2,%3}, [%4];"
                 : "=r"(r[0]), "=r"(r[1]), "=r"(r[2]), "=r"(r[3]) : "r"(addr));
}
static __device__ __forceinline__ void mma_f16(float* d, const uint32_t* a,
                                               uint32_t b0, uint32_t b1) {
    asm volatile(
        "mma.sync.aligned.m16n8k16.row.col.f32.f16.f16.f32 "
        "{%0,%1,%2,%3}, {%4,%5,%6,%7}, {%8,%9}, {%0,%1,%2,%3};"
        : "+f"(d[0]), "+f"(d[1]), "+f"(d[2]), "+f"(d[3])
        : "r"(a[0]), "r"(a[1]), "r"(a[2]), "r"(a[3]), "r"(b0), "r"(b1));
}
static __device__ __forceinline__ float tanh_ap(float x) {
    float y;
    asm("tanh.approx.f32 %0, %1;" : "=f"(y) : "f"(x));
    return y;
}
static __device__ __forceinline__ float sig_ap(float x) {
    return fmaf(tanh_ap(0.5f * x), 0.5f, 0.5f);
}

// per-m-group split barrier (32 CTAs each; all CTAs co-resident)
static __device__ __forceinline__ void bar_arrive(int mgrp, int t) {
    __syncthreads();
    if (threadIdx.x == 0) {
        __threadfence();
        if (atomicAdd(&g_bar_cnt[mgrp * 32], 1u) == GRPSZ - 1) {
            g_bar_cnt[mgrp * 32] = 0;
            __threadfence();
            g_bar_gen[mgrp * 32] = (unsigned)(t + 1);
        }
    }
}
static __device__ __forceinline__ void bar_wait(int mgrp, int t) {
    if (threadIdx.x == 0) {
        while ((int)g_bar_gen[mgrp * 32] < t) { }
        __threadfence();
    }
    __syncthreads();
}

// ---------------- prep kernels ----------------
__global__ void zero_kernel() {
    int i = blockIdx.x * 256 + threadIdx.x;
    if (i < NGHH) g_h[0][i] = __float2half(0.0f);
    if (i < 4 * 32) { g_bar_cnt[i] = 0; g_bar_gen[i] = 0; }
}

__global__ void init_out_kernel(const float* __restrict__ b_lin, float* __restrict__ out) {
    int i = blockIdx.x * 256 + threadIdx.x;
    if (i < NT * NG) out[i] = b_lin[0];
}

__global__ void prep_bias_kernel(const float* __restrict__ b_ih, const float* __restrict__ b_hh) {
    int col = blockIdx.x * 256 + threadIdx.x;
    if (col >= HH) return;
    float4 v;
    v.x = b_ih[col] + b_hh[col];
    v.y = b_ih[HH + col] + b_hh[HH + col];
    v.z = b_ih[2 * HH + col] + b_hh[2 * HH + col];
    v.w = b_ih[3 * HH + col] + b_hh[3 * HH + col];
    g_biasp[col] = v;
}

// W' row r' = col*4 + gate; k cols 0..1023 from W_hh, 1024..1279 from W_ih (fused K)
__global__ void prep_W_kernel(const float* __restrict__ W_ih, const float* __restrict__ W_hh) {
    int k = blockIdx.x * 256 + threadIdx.x;
    int r = blockIdx.y;                       // old row: gate*1024 + col
    if (k >= KTOT) return;
    float v = (k < HH) ? W_hh[(size_t)r * HH + k]
                       : W_ih[(size_t)r * NX + (k - HH)];
    int gate = r >> 10, col = r & 1023;
    g_Wp[(size_t)(col * 4 + gate) * KTOT + k] = __float2half(v);
}

__global__ void prep_xm_kernel(const float* __restrict__ x, const float* __restrict__ maskX) {
    int idx = blockIdx.x * 256 + threadIdx.x;   // 0..NG*NX-1
    int t = blockIdx.y;
    size_t gi = (size_t)t * (NG * NX) + idx;
    g_xm[gi] = __float2half(x[gi] * maskX[idx]);
}

// ---------------- persistent fused LSTM: m64n64 warp tiles, k-split ----------------
// grid 128 = 4 m-groups(128 batch) x 32 col-groups(128 N)
// 8 warps: quadrant q = w&3 -> (mq, nq), k-half = w>>2 (ks 0-1 vs 2-3)
__global__ __launch_bounds__(256, 1) void lstm_persist_kernel(
    const float* __restrict__ W_lin, float* __restrict__ out) {
    extern __shared__ char dsm[];
    const uint32_t sbase = smem_u32(dsm);
    float* sT = (float*)(dsm + SMEM_ST_OFF);
    const int tid = threadIdx.x;
    const int w = tid >> 5;
    const int lane = tid & 31;
    const int mgrp = blockIdx.x & 3;
    const int m0 = mgrp * 128;
    const int cgrp = blockIdx.x >> 2;
    const int n0g = cgrp * 128;

    const int prow = tid >> 3;                  // cp.async: 0..31 (+32*s)
    const int pseg = tid & 7;

    const int kh = w >> 2;                      // k-half: ks pair base
    const int mq = (w & 1) * 64;                // quadrant m-offset
    const int nq = ((w >> 1) & 1) * 64;         // quadrant n-offset
    const int lrow = lane & 15;
    const int lcol16 = (lane >> 4) * 16;

    const int tg = tid & 15;                    // epilogue col-pair group
    const int rr = tid >> 4;                    // epilogue row group (0..15)

    const int ecol = cgrp * 32 + tg * 2;
    const float4 bb0 = g_biasp[ecol];
    const float4 bb1 = g_biasp[ecol + 1];
    const float wl0 = W_lin[ecol];
    const float wl1 = W_lin[ecol + 1];

    float creg[8][2];
#pragma unroll
    for (int p = 0; p < 8; ++p) { creg[p][0] = 0.0f; creg[p][1] = 0.0f; }

    // chunk order: i=0..3 -> xm (no h dependency), i=4..19 -> h(t-1)
    auto prefetch = [&](int tt, int i, int stage) {
        const uint32_t stb = sbase + stage * STAGE_BYTES;
        const __half* aSrc;
        int astr, ak, bk;
        if (i < 4) {
            aSrc = g_xm + (size_t)tt * NG * NX; astr = NX; ak = i * 64; bk = (16 + i) * 64;
        } else {
            aSrc = g_h[tt & 1]; astr = HH; ak = (i - 4) * 64; bk = (i - 4) * 64;
        }
#pragma unroll
        for (int s = 0; s < 4; ++s) {
            const int row = prow + s * 32;
            const uint32_t soff = SWZ(row * 128 + pseg * 16);
            cp16(stb + soff,         aSrc + (size_t)(m0 + row) * astr + ak + pseg * 8);
            cp16(stb + 16384 + soff, g_Wp + (size_t)(n0g + row) * KTOT + bk + pseg * 8);
        }
        cp_commit();
    };

    // prologue for t=0 (later steps: chunks 0,1 issued in prior epilogue)
    prefetch(0, 0, 0);
    prefetch(0, 1, 1);

#pragma unroll 1
    for (int t = 0; t < NT; ++t) {
        const int wbuf = (t + 1) & 1;

        prefetch(t, 2, 2);                      // x chunk, stage 2 (free: held chunk 18)

        float acc[4][8][4];                     // m64 x n64: 4 m16-bands x 8 n8-bands
#pragma unroll
        for (int ia = 0; ia < 4; ++ia)
#pragma unroll
            for (int jn = 0; jn < 8; ++jn)
#pragma unroll
                for (int r = 0; r < 4; ++r) acc[ia][jn][r] = 0.0f;

        for (int i = 0; i < NCHUNK; ++i) {
            if (i == 18) cp_wait<1>();
            else if (i == 19) cp_wait<0>();
            else cp_wait<2>();                  // pending i..i+2 -> chunk i landed
            __syncthreads();
            if (i + 3 < NCHUNK) {
                if (i + 3 == 4) bar_wait(mgrp, t);   // h(t-1) complete before h prefetch
                int ns = i + 3; ns &= 3;
                prefetch(t, i + 3, ns);
            }

            const uint32_t stb = sbase + (i & 3) * STAGE_BYTES;
#pragma unroll
            for (int kss = 0; kss < 2; ++kss) {  // this warp's two K=16 sub-blocks
                const int kb = (kh * 2 + kss) * 32;
                uint32_t ah[4][4], bh[4][4];
#pragma unroll
                for (int ia = 0; ia < 4; ++ia)
                    ldm4(ah[ia], stb + SWZ((mq + ia * 16 + lrow) * 128 + kb + lcol16));
#pragma unroll
                for (int jb = 0; jb < 4; ++jb)
                    ldm4(bh[jb], stb + 16384 + SWZ((nq + jb * 16 + lrow) * 128 + kb + lcol16));
#pragma unroll
                for (int ia = 0; ia < 4; ++ia)
#pragma unroll
                    for (int jn = 0; jn < 8; ++jn)
                        mma_f16(acc[ia][jn], ah[ia], bh[jn >> 1][jn & 1], bh[jn >> 1][(jn & 1) + 2]);
            }
        }

        __syncthreads();                        // all warps done reading stages

        // issue next step's first x-chunk prefetches; land during epilogue
        if (t + 1 < NT) {
            prefetch(t + 1, 0, 0);
            prefetch(t + 1, 1, 1);
        }

        // ---- epilogue: k-split reduction into sT, then cell update ----
        // phase A: k-half 0 warps (0-3) write their quadrants
        if (w < 4) {
#pragma unroll
            for (int ia = 0; ia < 4; ++ia) {
                const int r0 = mq + ia * 16 + (lane >> 2);
#pragma unroll
                for (int jn = 0; jn < 8; ++jn) {
                    const int nb = nq + jn * 8 + (lane & 3) * 2;
                    *(float2*)&sT[r0 * 132 + nb]       = make_float2(acc[ia][jn][0], acc[ia][jn][1]);
                    *(float2*)&sT[(r0 + 8) * 132 + nb] = make_float2(acc[ia][jn][2], acc[ia][jn][3]);
                }
            }
        }
        __syncthreads();
        // phase B: k-half 1 warps (4-7) accumulate
        if (w >= 4) {
#pragma unroll
            for (int ia = 0; ia < 4; ++ia) {
                const int r0 = mq + ia * 16 + (lane >> 2);
#pragma unroll
                for (int jn = 0; jn < 8; ++jn) {
                    const int nb = nq + jn * 8 + (lane & 3) * 2;
                    float2 u = *(float2*)&sT[r0 * 132 + nb];
                    u.x += acc[ia][jn][0]; u.y += acc[ia][jn][1];
                    *(float2*)&sT[r0 * 132 + nb] = u;
                    float2 v = *(float2*)&sT[(r0 + 8) * 132 + nb];
                    v.x += acc[ia][jn][2]; v.y += acc[ia][jn][3];
                    *(float2*)&sT[(r0 + 8) * 132 + nb] = v;
                }
            }
        }
        __syncthreads();

#pragma unroll
        for (int p = 0; p < 8; ++p) {
            const int row = p * 16 + rr;
            const int b = m0 + row;
            const float4 gA = *(float4*)&sT[row * 132 + tg * 8];
            const float4 gB = *(float4*)&sT[row * 132 + tg * 8 + 4];

            float i0 = sig_ap(gA.x + bb0.x);
            float f0 = sig_ap(gA.y + bb0.y);
            float q0 = tanh_ap(gA.z + bb0.z);
            float o0 = sig_ap(gA.w + bb0.w);
            float i1 = sig_ap(gB.x + bb1.x);
            float f1 = sig_ap(gB.y + bb1.y);
            float q1 = tanh_ap(gB.z + bb1.z);
            float o1 = sig_ap(gB.w + bb1.w);

            float cn0 = f0 * creg[p][0] + i0 * q0;
            float cn1 = f1 * creg[p][1] + i1 * q1;
            creg[p][0] = cn0;
            creg[p][1] = cn1;
            float h0 = o0 * tanh_ap(cn0);
            float h1 = o1 * tanh_ap(cn1);

            *(__half2*)&g_h[wbuf][(size_t)b * HH + ecol] = __floats2half2_rn(h0, h1);

            float v = h0 * wl0 + h1 * wl1;
#pragma unroll
            for (int o = 8; o; o >>= 1)
                v += __shfl_xor_sync(0xFFFFFFFFu, v, o);
            if (tg == 0) atomicAdd(&out[t * NG + b], v);
        }

        bar_arrive(mgrp, t);                    // release h(t) for this m-group
    }
}

// ---------------- host ----------------
extern "C" void kernel_launch(void* const* d_in, const int* in_sizes, int n_in,
                              void* d_out, int out_size) {
    const float* x     = (const float*)d_in[0];
    const float* maskX = (const float*)d_in[1];
    const float* W_ih  = (const float*)d_in[2];
    const float* W_hh  = (const float*)d_in[3];
    const float* b_ih  = (const float*)d_in[4];
    const float* b_hh  = (const float*)d_in[5];
    const float* W_lin = (const float*)d_in[6];
    const float* b_lin = (const float*)d_in[7];
    float* out = (float*)d_out;

    cudaFuncSetAttribute(lstm_persist_kernel,
                         cudaFuncAttributeMaxDynamicSharedMemorySize, DSMEM_BYTES);

    zero_kernel<<<(NGHH + 255) / 256, 256>>>();
    init_out_kernel<<<(NT * NG + 255) / 256, 256>>>(b_lin, out);
    prep_bias_kernel<<<(HH + 255) / 256, 256>>>(b_ih, b_hh);
    prep_W_kernel<<<dim3((KTOT + 255) / 256, G4), 256>>>(W_ih, W_hh);
    prep_xm_kernel<<<dim3((NG * NX) / 256, NT), 256>>>(x, maskX);

    lstm_persist_kernel<<<NBLK, 256, DSMEM_BYTES>>>(W_lin, out);
}

// round 12
// speedup vs baseline: 1.0028x; 1.0028x over previous
#include <cuda_runtime.h>
#include <cuda_fp16.h>
#include <stdint.h>
#include <math.h>

#define NT 365
#define NG 512
#define NX 256
#define HH 1024
#define KTOT 1280
#define G4 4096
#define NGHH (NG * HH)
#define NCHUNK 20                    // 4 chunks of xm (K=256) first, then 16 of h (K=1024)
#define STAGE_BYTES 32768            // A(16KB) + B(16KB)
#define NSTAGE 3
#define SMEM_ST_OFF (NSTAGE * STAGE_BYTES)
#define DSMEM_BYTES (SMEM_ST_OFF + 128 * 132 * 4)   // stages + dedicated sT = 162KB
#define NBLK 128
#define GRPSZ 32                     // CTAs per m-group barrier

// ---------------- scratch (__device__ globals; no allocation) ----------------
__device__ __half g_h[2][NGHH];                     // ping-pong, fp16
__device__ __half g_Wp[(size_t)G4 * KTOT];          // rows permuted: r' = col*4 + gate
__device__ __half g_xm[(size_t)NT * NG * NX];       // fp16
__device__ float4 g_biasp[HH];                      // per col: (bi, bf, bg, bo)
__device__ unsigned int g_bar_cnt[4 * 32];          // per m-group, padded
__device__ volatile unsigned int g_bar_gen[4 * 32];

// ---------------- PTX helpers ----------------
static __device__ __forceinline__ uint32_t smem_u32(const void* p) {
    uint32_t a;
    asm("{ .reg .u64 t; cvta.to.shared.u64 t, %1; cvt.u32.u64 %0, t; }" : "=r"(a) : "l"(p));
    return a;
}
#define SWZ(o) ((o) ^ (((o) >> 3) & 0x70))

static __device__ __forceinline__ void cp16(uint32_t dst, const void* src) {
    asm volatile("cp.async.cg.shared.global [%0], [%1], 16;" :: "r"(dst), "l"(src));
}
static __device__ __forceinline__ void cp_commit() {
    asm volatile("cp.async.commit_group;" ::: "memory");
}
template <int N>
static __device__ __forceinline__ void cp_wait() {
    asm volatile("cp.async.wait_group %0;" :: "n"(N) : "memory");
}
static __device__ __forceinline__ void ldm4(uint32_t* r, uint32_t addr) {
    asm volatile("ldmatrix.sync.aligned.m8n8.x4.shared.b16 {%0,%1,%2,%3}, [%4];"
                 : "=r"(r[0]), "=r"(r[1]), "=r"(r[2]), "=r"(r[3]) : "r"(addr));
}
// fp16-accumulate HMMA: D(f16x2 x2) = A*B + D
static __device__ __forceinline__ void mma_f16acc(uint32_t* d, const uint32_t* a,
                                                  uint32_t b0, uint32_t b1) {
    asm volatile(
        "mma.sync.aligned.m16n8k16.row.col.f16.f16.f16.f16 "
        "{%0,%1}, {%2,%3,%4,%5}, {%6,%7}, {%0,%1};"
        : "+r"(d[0]), "+r"(d[1])
        : "r"(a[0]), "r"(a[1]), "r"(a[2]), "r"(a[3]), "r"(b0), "r"(b1));
}
static __device__ __forceinline__ float tanh_ap(float x) {
    float y;
    asm("tanh.approx.f32 %0, %1;" : "=f"(y) : "f"(x));
    return y;
}
static __device__ __forceinline__ float sig_ap(float x) {
    return fmaf(tanh_ap(0.5f * x), 0.5f, 0.5f);
}

// per-m-group split barrier (32 CTAs each; all CTAs co-resident)
static __device__ __forceinline__ void bar_arrive(int mgrp, int t) {
    __syncthreads();
    if (threadIdx.x == 0) {
        __threadfence();
        if (atomicAdd(&g_bar_cnt[mgrp * 32], 1u) == GRPSZ - 1) {
            g_bar_cnt[mgrp * 32] = 0;
            __threadfence();
            g_bar_gen[mgrp * 32] = (unsigned)(t + 1);
        }
    }
}
static __device__ __forceinline__ void bar_wait(int mgrp, int t) {
    if (threadIdx.x == 0) {
        while ((int)g_bar_gen[mgrp * 32] < t) { }
        __threadfence();
    }
    __syncthreads();
}

// ---------------- prep kernels ----------------
__global__ void zero_kernel() {
    int i = blockIdx.x * 256 + threadIdx.x;
    if (i < NGHH) g_h[0][i] = __float2half(0.0f);
    if (i < 4 * 32) { g_bar_cnt[i] = 0; g_bar_gen[i] = 0; }
}

__global__ void init_out_kernel(const float* __restrict__ b_lin, float* __restrict__ out) {
    int i = blockIdx.x * 256 + threadIdx.x;
    if (i < NT * NG) out[i] = b_lin[0];
}

__global__ void prep_bias_kernel(const float* __restrict__ b_ih, const float* __restrict__ b_hh) {
    int col = blockIdx.x * 256 + threadIdx.x;
    if (col >= HH) return;
    float4 v;
    v.x = b_ih[col] + b_hh[col];
    v.y = b_ih[HH + col] + b_hh[HH + col];
    v.z = b_ih[2 * HH + col] + b_hh[2 * HH + col];
    v.w = b_ih[3 * HH + col] + b_hh[3 * HH + col];
    g_biasp[col] = v;
}

// W' row r' = col*4 + gate; k cols 0..1023 from W_hh, 1024..1279 from W_ih (fused K)
__global__ void prep_W_kernel(const float* __restrict__ W_ih, const float* __restrict__ W_hh) {
    int k = blockIdx.x * 256 + threadIdx.x;
    int r = blockIdx.y;                       // old row: gate*1024 + col
    if (k >= KTOT) return;
    float v = (k < HH) ? W_hh[(size_t)r * HH + k]
                       : W_ih[(size_t)r * NX + (k - HH)];
    int gate = r >> 10, col = r & 1023;
    g_Wp[(size_t)(col * 4 + gate) * KTOT + k] = __float2half(v);
}

__global__ void prep_xm_kernel(const float* __restrict__ x, const float* __restrict__ maskX) {
    int idx = blockIdx.x * 256 + threadIdx.x;   // 0..NG*NX-1
    int t = blockIdx.y;
    size_t gi = (size_t)t * (NG * NX) + idx;
    g_xm[gi] = __float2half(x[gi] * maskX[idx]);
}

// ---------------- persistent fused LSTM: fp16-acc mma + periodic fp32 promote ----------------
// grid 128 = 4 m-groups(128 batch) x 32 col-groups(32 hidden cols x 4 gates = 128 N)
__global__ __launch_bounds__(256, 1) void lstm_persist_kernel(
    const float* __restrict__ W_lin, float* __restrict__ out) {
    extern __shared__ char dsm[];
    const uint32_t sbase = smem_u32(dsm);
    float* sT = (float*)(dsm + SMEM_ST_OFF);    // dedicated epilogue buffer
    const int tid = threadIdx.x;
    const int w = tid >> 5;
    const int lane = tid & 31;
    const int mgrp = blockIdx.x & 3;
    const int m0 = mgrp * 128;
    const int cgrp = blockIdx.x >> 2;
    const int n0g = cgrp * 128;

    const int prow = tid >> 3;                  // cp.async: 0..31 (+32*s)
    const int pseg = tid & 7;

    const int mw = (w & 3) * 32;                // warp m-offset
    const int nw = (w >> 2) * 64;               // warp n-offset
    const int lrow = lane & 15;
    const int lcol16 = (lane >> 4) * 16;

    const int tg = tid & 15;                    // epilogue col-pair group
    const int rr = tid >> 4;                    // epilogue row group (0..15)

    const int ecol = cgrp * 32 + tg * 2;
    const float4 bb0 = g_biasp[ecol];
    const float4 bb1 = g_biasp[ecol + 1];
    const float wl0 = W_lin[ecol];
    const float wl1 = W_lin[ecol + 1];

    float creg[8][2];                           // cell state, register-resident
#pragma unroll
    for (int p = 0; p < 8; ++p) { creg[p][0] = 0.0f; creg[p][1] = 0.0f; }

    // chunk order: i=0..3 -> xm (no h dependency), i=4..19 -> h(t-1)
    auto prefetch = [&](int tt, int i, int stage) {
        const uint32_t stb = sbase + stage * STAGE_BYTES;
        const __half* aSrc;
        int astr, ak, bk;
        if (i < 4) {
            aSrc = g_xm + (size_t)tt * NG * NX; astr = NX; ak = i * 64; bk = (16 + i) * 64;
        } else {
            aSrc = g_h[tt & 1]; astr = HH; ak = (i - 4) * 64; bk = (i - 4) * 64;
        }
#pragma unroll
        for (int s = 0; s < 4; ++s) {
            const int row = prow + s * 32;
            const uint32_t soff = SWZ(row * 128 + pseg * 16);
            cp16(stb + soff,         aSrc + (size_t)(m0 + row) * astr + ak + pseg * 8);
            cp16(stb + 16384 + soff, g_Wp + (size_t)(n0g + row) * KTOT + bk + pseg * 8);
        }
        cp_commit();
    };

    prefetch(0, 0, 0);
    prefetch(0, 1, 1);

#pragma unroll 1
    for (int t = 0; t < NT; ++t) {
        const int wbuf = (t + 1) & 1;

        float acc[2][8][4];                     // fp32 accumulators
        uint32_t hacc[2][8][2];                 // fp16x2 group accumulators
#pragma unroll
        for (int im = 0; im < 2; ++im)
#pragma unroll
            for (int jn = 0; jn < 8; ++jn) {
#pragma unroll
                for (int r = 0; r < 4; ++r) acc[im][jn][r] = 0.0f;
                hacc[im][jn][0] = 0u; hacc[im][jn][1] = 0u;
            }

        int stage = 0;
        for (int i = 0; i < NCHUNK; ++i) {
            if (i + 1 < NCHUNK) cp_wait<1>();   // chunk i landed (i+1 may be pending)
            else cp_wait<0>();
            __syncthreads();                     // data visible + compute(i-1) done
            if (i + 2 < NCHUNK) {
                if (i + 2 == 4) bar_wait(mgrp, t);  // h(t-1) complete before h prefetch
                int ns = stage + 2; if (ns >= NSTAGE) ns -= NSTAGE;
                prefetch(t, i + 2, ns);
            }

            const uint32_t stb = sbase + stage * STAGE_BYTES;
#pragma unroll
            for (int ks = 0; ks < 4; ++ks) {     // K=16 per mma, 4 per 64-chunk
                const int kb = ks * 32;
                uint32_t ah[2][4], bh[4][4];
#pragma unroll
                for (int im = 0; im < 2; ++im)
                    ldm4(ah[im], stb + SWZ((mw + im * 16 + lrow) * 128 + kb + lcol16));
#pragma unroll
                for (int jb = 0; jb < 4; ++jb)
                    ldm4(bh[jb], stb + 16384 + SWZ((nw + jb * 16 + lrow) * 128 + kb + lcol16));
#pragma unroll
                for (int im = 0; im < 2; ++im)
#pragma unroll
                    for (int jn = 0; jn < 8; ++jn)
                        mma_f16acc(hacc[im][jn], ah[im],
                                   bh[jn >> 1][jn & 1], bh[jn >> 1][(jn & 1) + 2]);
            }
            // promote fp16 group accum -> fp32 every 2 chunks (K=128 groups)
            if (i & 1) {
#pragma unroll
                for (int im = 0; im < 2; ++im)
#pragma unroll
                    for (int jn = 0; jn < 8; ++jn) {
                        float2 lo = __half22float2(*(__half2*)&hacc[im][jn][0]);
                        float2 hi = __half22float2(*(__half2*)&hacc[im][jn][1]);
                        acc[im][jn][0] += lo.x; acc[im][jn][1] += lo.y;
                        acc[im][jn][2] += hi.x; acc[im][jn][3] += hi.y;
                        hacc[im][jn][0] = 0u; hacc[im][jn][1] = 0u;
                    }
            }
            ++stage; if (stage >= NSTAGE) stage = 0;
        }

        __syncthreads();                        // all warps done reading stages

        // issue next step's x-chunk prefetches; land during epilogue
        if (t + 1 < NT) {
            prefetch(t + 1, 0, 0);
            prefetch(t + 1, 1, 1);
        }

        // ---- epilogue: fragments -> sT (transpose) -> cell update + fused out dot ----
#pragma unroll
        for (int im = 0; im < 2; ++im) {
            const int r0 = mw + im * 16 + (lane >> 2);
#pragma unroll
            for (int jn = 0; jn < 8; ++jn) {
                const int nb = nw + jn * 8 + (lane & 3) * 2;
                *(float2*)&sT[r0 * 132 + nb]       = make_float2(acc[im][jn][0], acc[im][jn][1]);
                *(float2*)&sT[(r0 + 8) * 132 + nb] = make_float2(acc[im][jn][2], acc[im][jn][3]);
            }
        }
        __syncthreads();

#pragma unroll
        for (int p = 0; p < 8; ++p) {
            const int row = p * 16 + rr;
            const int b = m0 + row;
            const float4 gA = *(float4*)&sT[row * 132 + tg * 8];
            const float4 gB = *(float4*)&sT[row * 132 + tg * 8 + 4];

            float i0 = sig_ap(gA.x + bb0.x);
            float f0 = sig_ap(gA.y + bb0.y);
            float q0 = tanh_ap(gA.z + bb0.z);
            float o0 = sig_ap(gA.w + bb0.w);
            float i1 = sig_ap(gB.x + bb1.x);
            float f1 = sig_ap(gB.y + bb1.y);
            float q1 = tanh_ap(gB.z + bb1.z);
            float o1 = sig_ap(gB.w + bb1.w);

            float cn0 = f0 * creg[p][0] + i0 * q0;
            float cn1 = f1 * creg[p][1] + i1 * q1;
            creg[p][0] = cn0;
            creg[p][1] = cn1;
            float h0 = o0 * tanh_ap(cn0);
            float h1 = o1 * tanh_ap(cn1);

            *(__half2*)&g_h[wbuf][(size_t)b * HH + ecol] = __floats2half2_rn(h0, h1);

            float v = h0 * wl0 + h1 * wl1;
#pragma unroll
            for (int o = 8; o; o >>= 1)
                v += __shfl_xor_sync(0xFFFFFFFFu, v, o);
            if (tg == 0) atomicAdd(&out[t * NG + b], v);
        }

        bar_arrive(mgrp, t);                    // release h(t) for this m-group
    }
}

// ---------------- host ----------------
extern "C" void kernel_launch(void* const* d_in, const int* in_sizes, int n_in,
                              void* d_out, int out_size) {
    const float* x     = (const float*)d_in[0];
    const float* maskX = (const float*)d_in[1];
    const float* W_ih  = (const float*)d_in[2];
    const float* W_hh  = (const float*)d_in[3];
    const float* b_ih  = (const float*)d_in[4];
    const float* b_hh  = (const float*)d_in[5];
    const float* W_lin = (const float*)d_in[6];
    const float* b_lin = (const float*)d_in[7];
    float* out = (float*)d_out;

    cudaFuncSetAttribute(lstm_persist_kernel,
                         cudaFuncAttributeMaxDynamicSharedMemorySize, DSMEM_BYTES);

    zero_kernel<<<(NGHH + 255) / 256, 256>>>();
    init_out_kernel<<<(NT * NG + 255) / 256, 256>>>(b_lin, out);
    prep_bias_kernel<<<(HH + 255) / 256, 256>>>(b_ih, b_hh);
    prep_W_kernel<<<dim3((KTOT + 255) / 256, G4), 256>>>(W_ih, W_hh);
    prep_xm_kernel<<<dim3((NG * NX) / 256, NT), 256>>>(x, maskX);

    lstm_persist_kernel<<<NBLK, 256, DSMEM_BYTES>>>(W_lin, out);
}